// round 12
// baseline (speedup 1.0000x reference)
#include <cuda_runtime.h>
#include <cuda_bf16.h>
#include <math.h>
#include <stdint.h>

// Problem constants
#define S 2048
#define H 2048
#define NH 16
#define HD 128
#define QKV_N (3 * H)         // 6144
#define MIXED_W (3 * HD * NH) // 6144
#define HEAD_W (3 * HD)       // 384

// Scratch
__device__ float g_mixed[(size_t)S * QKV_N];
__device__ float g_ctx[(size_t)S * H];
__device__ float g_hidden_t[(size_t)S * H];
__device__ float g_wqkv_t[(size_t)QKV_N * H];
__device__ float g_wdense_t[(size_t)H * H];

// ---------------------------------------------------------------------------
// Helpers
// ---------------------------------------------------------------------------
__device__ __forceinline__ uint32_t smem_to_u32(const void* p) {
    uint32_t a;
    asm("{ .reg .u64 t; cvta.to.shared.u64 t, %1; cvt.u32.u64 %0, t; }" : "=r"(a) : "l"(p));
    return a;
}
__device__ __forceinline__ uint32_t f32_to_tf32(float f) {
    uint32_t r;
    asm("cvt.rna.tf32.f32 %0, %1;" : "=r"(r) : "f"(f));
    return r;
}
__device__ __forceinline__ float tf32_round(float f) {
    return __uint_as_float(f32_to_tf32(f));
}
#define CP_ASYNC16(dst, src) \
    asm volatile("cp.async.cg.shared.global [%0], [%1], 16;" :: "r"(dst), "l"(src) : "memory")
#define CP_ASYNC_COMMIT() asm volatile("cp.async.commit_group;" ::: "memory")
#define CP_ASYNC_WAIT(n)  asm volatile("cp.async.wait_group %0;" :: "n"(n) : "memory")

__device__ __forceinline__ void mma_tf32(
    float c[4], const uint32_t a[4], const uint32_t b[2])
{
    asm volatile(
        "mma.sync.aligned.m16n8k8.row.col.f32.tf32.tf32.f32 "
        "{%0,%1,%2,%3}, {%4,%5,%6,%7}, {%8,%9}, {%0,%1,%2,%3};"
        : "+f"(c[0]), "+f"(c[1]), "+f"(c[2]), "+f"(c[3])
        : "r"(a[0]), "r"(a[1]), "r"(a[2]), "r"(a[3]), "r"(b[0]), "r"(b[1]));
}
__device__ __forceinline__ uint32_t f4c(const float4& v, int j) {
    const float* p = (const float*)&v;
    return __float_as_uint(p[j]);
}

// ---------------------------------------------------------------------------
// Elementwise tf32 pre-round (grid-stride, float4)
// ---------------------------------------------------------------------------
__global__ void round_tf32_kernel(const float4* __restrict__ in,
                                  float4* __restrict__ out, int n4)
{
    for (int i = blockIdx.x * blockDim.x + threadIdx.x; i < n4;
         i += gridDim.x * blockDim.x) {
        float4 v = in[i];
        v.x = tf32_round(v.x); v.y = tf32_round(v.y);
        v.z = tf32_round(v.z); v.w = tf32_round(v.w);
        out[i] = v;
    }
}

// ---------------------------------------------------------------------------
// tf32 mma.sync GEMM: C[M,N] = A[M,K]*B[N,K]^T (+bias)
// Pre-rounded inputs -> no cvt. BM=128, BN=256, BK=32, 256 threads
// (8 warps, 2x4 grid of 64x64 warp tiles). 3-stage cp.async pipeline,
// one __syncthreads per k-chunk. Stride 36: conflict-free scalar LDS.
// ---------------------------------------------------------------------------
#define TSTR 36
#define AWORDS (128 * TSTR)                      // 4608
#define BWORDS (256 * TSTR)                      // 9216
#define STAGE_WORDS (AWORDS + BWORDS)            // 13824
#define GT_SMEM_BYTES (3 * STAGE_WORDS * 4)      // 165888

__global__ __launch_bounds__(256) void gemm_tc_kernel(
    const float* __restrict__ A, const float* __restrict__ B,
    const float* __restrict__ bias, float* __restrict__ C,
    int M, int N, int K)
{
    extern __shared__ float smf[];
    const uint32_t smem_base = smem_to_u32(smf);
    const int tid  = threadIdx.x;
    const int wid  = tid >> 5;
    const int lane = tid & 31;
    const int wm = wid >> 2;         // 0..1 (64-row strip in BM=128)
    const int wn = wid & 3;          // 0..3 (64-col strip in BN=256)
    const int bm = blockIdx.y * 128;
    const int bn = blockIdx.x * 256;

    const int lr = lane >> 2;
    const int lc = lane & 3;

    const int ld_row = tid >> 3;         // 0..31
    const int ld_k4  = (tid & 7) << 2;

    float c[4][8][4];
#pragma unroll
    for (int mt = 0; mt < 4; mt++)
#pragma unroll
        for (int nt = 0; nt < 8; nt++)
#pragma unroll
            for (int r = 0; r < 4; r++) c[mt][nt][r] = 0.f;

    const int NK = K >> 5;

    auto load_tiles = [&](int i) {
        const int st = i % 3;
        const int k0 = i << 5;
        const uint32_t abase = smem_base + (uint32_t)(st * STAGE_WORDS) * 4;
        const uint32_t bbase = abase + AWORDS * 4;
#pragma unroll
        for (int j = 0; j < 4; j++) {
            const int m = ld_row + 32 * j;
            const uint32_t soff = (uint32_t)(m * TSTR + ld_k4) * 4;
            CP_ASYNC16(abase + soff, A + (size_t)(bm + m) * K + k0 + ld_k4);
        }
#pragma unroll
        for (int j = 0; j < 8; j++) {
            const int n = ld_row + 32 * j;
            const uint32_t soff = (uint32_t)(n * TSTR + ld_k4) * 4;
            CP_ASYNC16(bbase + soff, B + (size_t)(bn + n) * K + k0 + ld_k4);
        }
        CP_ASYNC_COMMIT();
    };

    load_tiles(0);
    load_tiles(1);

    for (int i = 0; i < NK; i++) {
        CP_ASYNC_WAIT(1);
        __syncthreads();

        const float* As = smf + (size_t)(i % 3) * STAGE_WORDS;
        const float* Bs = As + AWORDS;

#pragma unroll
        for (int ks = 0; ks < 4; ks++) {
            const int kc = ks * 8 + lc;
            uint32_t af[4][4];
#pragma unroll
            for (int mt = 0; mt < 4; mt++) {
                const int row = wm * 64 + mt * 16 + lr;
                af[mt][0] = __float_as_uint(As[row * TSTR + kc]);
                af[mt][1] = __float_as_uint(As[(row + 8) * TSTR + kc]);
                af[mt][2] = __float_as_uint(As[row * TSTR + kc + 4]);
                af[mt][3] = __float_as_uint(As[(row + 8) * TSTR + kc + 4]);
            }
            uint32_t bf[8][2];
#pragma unroll
            for (int nt = 0; nt < 8; nt++) {
                const int ncol = wn * 64 + nt * 8 + lr;
                bf[nt][0] = __float_as_uint(Bs[ncol * TSTR + kc]);
                bf[nt][1] = __float_as_uint(Bs[ncol * TSTR + kc + 4]);
            }
#pragma unroll
            for (int mt = 0; mt < 4; mt++)
#pragma unroll
                for (int nt = 0; nt < 8; nt++)
                    mma_tf32(c[mt][nt], af[mt], bf[nt]);
        }

        if (i + 2 < NK) load_tiles(i + 2);
    }

#pragma unroll
    for (int nt = 0; nt < 8; nt++) {
        const int col = bn + wn * 64 + nt * 8 + lc * 2;
        float b0 = 0.f, b1 = 0.f;
        if (bias) { b0 = bias[col]; b1 = bias[col + 1]; }
#pragma unroll
        for (int mt = 0; mt < 4; mt++) {
            const int row = bm + wm * 64 + mt * 16 + lr;
            float2 v0 = make_float2(c[mt][nt][0] + b0, c[mt][nt][1] + b1);
            float2 v1 = make_float2(c[mt][nt][2] + b0, c[mt][nt][3] + b1);
            *(float2*)(C + (size_t)row * N + col) = v0;
            *(float2*)(C + (size_t)(row + 8) * N + col) = v1;
        }
    }
}

// ---------------------------------------------------------------------------
// Rotary embedding + tf32 pre-round + q pre-scale
// ---------------------------------------------------------------------------
__global__ void rotary_kernel(float* __restrict__ mixed)
{
    const int s = blockIdx.x;
    const int n = blockIdx.y;
    const int d = threadIdx.x;  // 0..63
    const float inv_freq = expf(-(float)d * (9.210340371976184f / 64.0f));
    const float freq = (float)s * inv_freq;
    float si, c;
    sincosf(freq, &si, &c);
    const float scale = 0.08838834764831845f;

    float* base = mixed + (size_t)s * MIXED_W + n * HEAD_W;
    {
        float* p = base;
        const float x1 = p[d];
        const float x2 = p[d + 64];
        p[d]      = tf32_round(scale * (x1 * c - x2 * si));
        p[d + 64] = tf32_round(scale * (x2 * c + x1 * si));
    }
    {
        float* p = base + HD;
        const float x1 = p[d];
        const float x2 = p[d + 64];
        p[d]      = tf32_round(x1 * c - x2 * si);
        p[d + 64] = tf32_round(x2 * c + x1 * si);
    }
    {
        float* p = base + 2 * HD;
        p[d]      = tf32_round(p[d]);
        p[d + 64] = tf32_round(p[d + 64]);
    }
}

// ---------------------------------------------------------------------------
// tf32 mma.sync flash attention (causal)  (unchanged, passing)
// ---------------------------------------------------------------------------
#define AQ 128
#define AK 64
#define QST 144
#define QST4 (QST / 4)
#define VST 136
#define QWRD (128 * QST)
#define KWRD (64 * QST)
#define VWRD (64 * VST)
#define ATTN_SMEM_BYTES ((QWRD + 2 * (KWRD + VWRD)) * 4)  // 217088 B

__global__ __launch_bounds__(256, 1) void attn_tc_kernel(
    const float* __restrict__ mixed, float* __restrict__ ctx)
{
    extern __shared__ float sf[];
    const uint32_t smem_base = smem_to_u32(sf);

    const int tid  = threadIdx.x;
    const int wid  = tid >> 5;
    const int lane = tid & 31;
    const int lr = lane >> 2;
    const int lc = lane & 3;
    const int qt = gridDim.x - 1 - blockIdx.x;
    const int h  = blockIdx.y;
    const int r0 = qt * AQ;
    const int m0 = wid * 16;
    const size_t hoff = (size_t)h * HEAD_W;

    auto load_kv = [&](int kt) {
        const int b = kt & 1;
        const uint32_t kb = smem_base + (uint32_t)(QWRD + b * (KWRD + VWRD)) * 4;
        const uint32_t vb = kb + KWRD * 4;
        const float* kg = mixed + (size_t)(kt * AK) * MIXED_W + hoff + HD;
        const float* vg = kg + HD;
#pragma unroll
        for (int it = 0; it < 8; it++) {
            const int u = tid + (it << 8);
            const int row = u >> 5, c4 = (u & 31) << 2;
            CP_ASYNC16(kb + (uint32_t)(row * QST + c4) * 4, kg + (size_t)row * MIXED_W + c4);
            CP_ASYNC16(vb + (uint32_t)(row * VST + c4) * 4, vg + (size_t)row * MIXED_W + c4);
        }
        CP_ASYNC_COMMIT();
    };

    load_kv(0);

    {
        const float* qg = mixed + (size_t)r0 * MIXED_W + hoff;
#pragma unroll
        for (int it = 0; it < 16; it++) {
            const int u = tid + (it << 8);
            const int row = u >> 5, c4 = (u & 31) << 2;
            CP_ASYNC16(smem_base + (uint32_t)(row * QST + c4) * 4,
                       qg + (size_t)row * MIXED_W + c4);
        }
        CP_ASYNC_COMMIT();
    }

    const int nkt = (r0 >> 6) + 2;

    float co[16][4];
#pragma unroll
    for (int nt = 0; nt < 16; nt++)
#pragma unroll
        for (int r = 0; r < 4; r++) co[nt][r] = 0.f;
    float mrow[2] = {-1e30f, -1e30f};
    float lrow[2] = {0.f, 0.f};

    const int src1 = (lane & ~3) | (lc >> 1);
    const int src2 = src1 + 2;
    const bool podd = (lc & 1);

    for (int kt = 0; kt < nkt; kt++) {
        if (kt + 1 < nkt) { load_kv(kt + 1); CP_ASYNC_WAIT(1); }
        else              { CP_ASYNC_WAIT(0); }
        __syncthreads();

        const float* Ks = sf + QWRD + (size_t)(kt & 1) * (KWRD + VWRD);
        const float* Vs = Ks + KWRD;
        const float4* Qs4 = (const float4*)sf;
        const float4* Ks4 = (const float4*)Ks;
        const int c0 = kt * AK;

        if (c0 <= r0 + m0 + 15) {
            float s[8][4];
#pragma unroll
            for (int nt = 0; nt < 8; nt++)
#pragma unroll
                for (int r = 0; r < 4; r++) s[nt][r] = 0.f;

#pragma unroll
            for (int ch = 0; ch < 4; ch++) {
                const int cb = ch * 8;
                const int row = m0 + lr;
                float4 qa[2][2];
                qa[0][0] = Qs4[row * QST4 + cb + lc];
                qa[0][1] = Qs4[row * QST4 + cb + 4 + lc];
                qa[1][0] = Qs4[(row + 8) * QST4 + cb + lc];
                qa[1][1] = Qs4[(row + 8) * QST4 + cb + 4 + lc];
#pragma unroll
                for (int g = 0; g < 2; g++) {
                    float4 kb4[4][2];
#pragma unroll
                    for (int q = 0; q < 4; q++) {
                        const int col = (g * 4 + q) * 8 + lr;
                        kb4[q][0] = Ks4[col * QST4 + cb + lc];
                        kb4[q][1] = Ks4[col * QST4 + cb + 4 + lc];
                    }
#pragma unroll
                    for (int j = 0; j < 4; j++) {
                        uint32_t a[4] = { f4c(qa[0][0], j), f4c(qa[1][0], j),
                                          f4c(qa[0][1], j), f4c(qa[1][1], j) };
#pragma unroll
                        for (int q = 0; q < 4; q++) {
                            uint32_t b[2] = { f4c(kb4[q][0], j), f4c(kb4[q][1], j) };
                            mma_tf32(s[g * 4 + q], a, b);
                        }
                    }
                }
            }

            if (c0 + AK - 1 > r0 + m0) {
                const int rga = r0 + m0 + lr;
                const int rgb = rga + 8;
#pragma unroll
                for (int nt = 0; nt < 8; nt++) {
                    const int cg0 = c0 + nt * 8 + lc * 2;
                    const int cg1 = cg0 + 1;
                    if (cg0 > rga) s[nt][0] = -1e30f;
                    if (cg1 > rga) s[nt][1] = -1e30f;
                    if (cg0 > rgb) s[nt][2] = -1e30f;
                    if (cg1 > rgb) s[nt][3] = -1e30f;
                }
            }

#pragma unroll
            for (int hh = 0; hh < 2; hh++) {
                float mx = -1e30f;
#pragma unroll
                for (int nt = 0; nt < 8; nt++)
                    mx = fmaxf(mx, fmaxf(s[nt][2 * hh], s[nt][2 * hh + 1]));
                mx = fmaxf(mx, __shfl_xor_sync(0xffffffffu, mx, 1));
                mx = fmaxf(mx, __shfl_xor_sync(0xffffffffu, mx, 2));
                const float m_new = fmaxf(mrow[hh], mx);
                const float sc = __expf(mrow[hh] - m_new);
                float rs = 0.f;
#pragma unroll
                for (int nt = 0; nt < 8; nt++) {
                    const float p0 = __expf(s[nt][2 * hh] - m_new);
                    const float p1 = __expf(s[nt][2 * hh + 1] - m_new);
                    s[nt][2 * hh] = p0;
                    s[nt][2 * hh + 1] = p1;
                    rs += p0 + p1;
                }
                rs += __shfl_xor_sync(0xffffffffu, rs, 1);
                rs += __shfl_xor_sync(0xffffffffu, rs, 2);
                lrow[hh] = lrow[hh] * sc + rs;
                mrow[hh] = m_new;
#pragma unroll
                for (int nt = 0; nt < 16; nt++) {
                    co[nt][2 * hh]     *= sc;
                    co[nt][2 * hh + 1] *= sc;
                }
            }

#pragma unroll
            for (int kg = 0; kg < 8; kg++) {
                uint32_t pa[4];
                {
                    const float x0 = __shfl_sync(0xffffffffu, s[kg][0], src1);
                    const float x1 = __shfl_sync(0xffffffffu, s[kg][1], src1);
                    pa[0] = f32_to_tf32(podd ? x1 : x0);
                    const float x2 = __shfl_sync(0xffffffffu, s[kg][2], src1);
                    const float x3 = __shfl_sync(0xffffffffu, s[kg][3], src1);
                    pa[1] = f32_to_tf32(podd ? x3 : x2);
                    const float y0 = __shfl_sync(0xffffffffu, s[kg][0], src2);
                    const float y1 = __shfl_sync(0xffffffffu, s[kg][1], src2);
                    pa[2] = f32_to_tf32(podd ? y1 : y0);
                    const float y2 = __shfl_sync(0xffffffffu, s[kg][2], src2);
                    const float y3 = __shfl_sync(0xffffffffu, s[kg][3], src2);
                    pa[3] = f32_to_tf32(podd ? y3 : y2);
                }
#pragma unroll
                for (int nt = 0; nt < 16; nt++) {
                    uint32_t vb[2];
                    vb[0] = __float_as_uint(Vs[(kg * 8 + lc) * VST + nt * 8 + lr]);
                    vb[1] = __float_as_uint(Vs[(kg * 8 + lc + 4) * VST + nt * 8 + lr]);
                    mma_tf32(co[nt], pa, vb);
                }
            }
        }
        __syncthreads();
    }

    {
        const float li0 = 1.f / lrow[0];
        const float li1 = 1.f / lrow[1];
        const int row = r0 + m0 + lr;
#pragma unroll
        for (int nt = 0; nt < 16; nt++) {
            const int col = h * HD + nt * 8 + lc * 2;
            *(float2*)(ctx + (size_t)row * H + col) =
                make_float2(tf32_round(co[nt][0] * li0), tf32_round(co[nt][1] * li0));
            *(float2*)(ctx + (size_t)(row + 8) * H + col) =
                make_float2(tf32_round(co[nt][2] * li1), tf32_round(co[nt][3] * li1));
        }
    }
}

// ---------------------------------------------------------------------------
// Launch
// ---------------------------------------------------------------------------
extern "C" void kernel_launch(void* const* d_in, const int* in_sizes, int n_in,
                              void* d_out, int out_size)
{
    const float* hidden  = (const float*)d_in[0];
    const float* w_qkv   = (const float*)d_in[2];
    const float* b_qkv   = (const float*)d_in[3];
    const float* w_dense = (const float*)d_in[4];
    float* out = (float*)d_out;

    float *mixed, *ctx, *hidden_t, *wqkv_t, *wdense_t;
    cudaGetSymbolAddress((void**)&mixed, g_mixed);
    cudaGetSymbolAddress((void**)&ctx, g_ctx);
    cudaGetSymbolAddress((void**)&hidden_t, g_hidden_t);
    cudaGetSymbolAddress((void**)&wqkv_t, g_wqkv_t);
    cudaGetSymbolAddress((void**)&wdense_t, g_wdense_t);

    cudaFuncSetAttribute(gemm_tc_kernel,
                         cudaFuncAttributeMaxDynamicSharedMemorySize, GT_SMEM_BYTES);
    cudaFuncSetAttribute(attn_tc_kernel,
                         cudaFuncAttributeMaxDynamicSharedMemorySize, ATTN_SMEM_BYTES);

    // 0) tf32 pre-round of GEMM operands
    round_tf32_kernel<<<2048, 256>>>((const float4*)hidden, (float4*)hidden_t,
                                     (S * H) / 4);
    round_tf32_kernel<<<2048, 256>>>((const float4*)w_qkv, (float4*)wqkv_t,
                                     (QKV_N * H) / 4);
    round_tf32_kernel<<<2048, 256>>>((const float4*)w_dense, (float4*)wdense_t,
                                     (H * H) / 4);

    // 1) QKV projection
    {
        dim3 grid(QKV_N / 256, S / 128);
        gemm_tc_kernel<<<grid, 256, GT_SMEM_BYTES>>>(hidden_t, wqkv_t, b_qkv,
                                                     mixed, S, QKV_N, H);
    }

    // 2) Rotary + tf32 pre-round of q/k/v
    {
        dim3 grid(S, NH);
        rotary_kernel<<<grid, 64>>>(mixed);
    }

    // 3) Causal flash attention
    {
        dim3 grid(S / AQ, NH);
        attn_tc_kernel<<<grid, 256, ATTN_SMEM_BYTES>>>(mixed, ctx);
    }

    // 4) Dense projection
    {
        dim3 grid(H / 256, S / 128);
        gemm_tc_kernel<<<grid, 256, GT_SMEM_BYTES>>>(ctx, wdense_t, nullptr,
                                                     out, S, H, H);
    }
}

// round 14
// speedup vs baseline: 1.7022x; 1.7022x over previous
#include <cuda_runtime.h>
#include <cuda_bf16.h>
#include <math.h>
#include <stdint.h>

// Problem constants
#define S 2048
#define H 2048
#define NH 16
#define HD 128
#define QKV_N (3 * H)         // 6144
#define MIXED_W (3 * HD * NH) // 6144
#define HEAD_W (3 * HD)       // 384

// Scratch
__device__ float g_mixed[(size_t)S * QKV_N];
__device__ float g_ctx[(size_t)S * H];
__device__ float g_hidden_t[(size_t)S * H];
__device__ float g_wqkv_t[(size_t)QKV_N * H];
__device__ float g_wdense_t[(size_t)H * H];

// ---------------------------------------------------------------------------
// Helpers
// ---------------------------------------------------------------------------
__device__ __forceinline__ uint32_t smem_to_u32(const void* p) {
    uint32_t a;
    asm("{ .reg .u64 t; cvta.to.shared.u64 t, %1; cvt.u32.u64 %0, t; }" : "=r"(a) : "l"(p));
    return a;
}
__device__ __forceinline__ uint32_t f32_to_tf32(float f) {
    uint32_t r;
    asm("cvt.rna.tf32.f32 %0, %1;" : "=r"(r) : "f"(f));
    return r;
}
__device__ __forceinline__ float tf32_round(float f) {
    return __uint_as_float(f32_to_tf32(f));
}
#define CP_ASYNC16(dst, src) \
    asm volatile("cp.async.cg.shared.global [%0], [%1], 16;" :: "r"(dst), "l"(src) : "memory")
#define CP_ASYNC_COMMIT() asm volatile("cp.async.commit_group;" ::: "memory")
#define CP_ASYNC_WAIT(n)  asm volatile("cp.async.wait_group %0;" :: "n"(n) : "memory")

__device__ __forceinline__ void mma_tf32(
    float c[4], const uint32_t a[4], const uint32_t b[2])
{
    asm volatile(
        "mma.sync.aligned.m16n8k8.row.col.f32.tf32.tf32.f32 "
        "{%0,%1,%2,%3}, {%4,%5,%6,%7}, {%8,%9}, {%0,%1,%2,%3};"
        : "+f"(c[0]), "+f"(c[1]), "+f"(c[2]), "+f"(c[3])
        : "r"(a[0]), "r"(a[1]), "r"(a[2]), "r"(a[3]), "r"(b[0]), "r"(b[1]));
}
__device__ __forceinline__ uint32_t f4c(const float4& v, int j) {
    const float* p = (const float*)&v;
    return __float_as_uint(p[j]);
}

// ---------------------------------------------------------------------------
// Fused tf32 pre-round of all three GEMM operand tensors (one launch)
// ---------------------------------------------------------------------------
#define N4_HID ((S * H) / 4)
#define N4_WQKV ((QKV_N * H) / 4)
#define N4_WD ((H * H) / 4)
#define N4_TOT (N4_HID + N4_WQKV + N4_WD)

__global__ void round_all_kernel(const float4* __restrict__ hid,
                                 const float4* __restrict__ wq,
                                 const float4* __restrict__ wd,
                                 float4* __restrict__ hid_o,
                                 float4* __restrict__ wq_o,
                                 float4* __restrict__ wd_o)
{
    for (int i = blockIdx.x * blockDim.x + threadIdx.x; i < N4_TOT;
         i += gridDim.x * blockDim.x) {
        const float4* src;
        float4* dst;
        int j = i;
        if (j < N4_HID) { src = hid; dst = hid_o; }
        else if (j < N4_HID + N4_WQKV) { j -= N4_HID; src = wq; dst = wq_o; }
        else { j -= N4_HID + N4_WQKV; src = wd; dst = wd_o; }
        float4 v = src[j];
        v.x = tf32_round(v.x); v.y = tf32_round(v.y);
        v.z = tf32_round(v.z); v.w = tf32_round(v.w);
        dst[j] = v;
    }
}

// ---------------------------------------------------------------------------
// tf32 mma.sync GEMM: C[M,N] = A[M,K]*B[N,K]^T (+bias)
// Pre-rounded inputs -> no cvt. BM=BN=128, BK=32, 256 threads
// (8 warps, 2x4 of 64x32 warp tiles). 3-stage cp.async pipeline,
// ONE barrier per k-chunk. Last iteration uses WAIT(0): in iteration i the
// newest committed group is min(i+1, NK-1); WAIT(1) only covers group i when
// a newer group exists, so the final iteration must drain fully (race fix).
// ---------------------------------------------------------------------------
#define TSTR 36
#define TILE_WORDS (128 * TSTR)                  // 4608
#define GT_SMEM_BYTES (6 * TILE_WORDS * 4)       // 110592

__global__ __launch_bounds__(256) void gemm_tc_kernel(
    const float* __restrict__ A, const float* __restrict__ B,
    const float* __restrict__ bias, float* __restrict__ C,
    int M, int N, int K)
{
    extern __shared__ float smf[];
    const uint32_t smem_base = smem_to_u32(smf);
    const int tid  = threadIdx.x;
    const int wid  = tid >> 5;
    const int lane = tid & 31;
    const int wm = wid >> 2;         // 0..1
    const int wn = wid & 3;          // 0..3
    const int bm = blockIdx.y * 128;
    const int bn = blockIdx.x * 128;

    const int lr = lane >> 2;
    const int lc = lane & 3;

    const int ld_row = tid >> 3;         // 0..31
    const int ld_k4  = (tid & 7) << 2;

    float c[4][4][4];
#pragma unroll
    for (int mt = 0; mt < 4; mt++)
#pragma unroll
        for (int nt = 0; nt < 4; nt++)
#pragma unroll
            for (int r = 0; r < 4; r++) c[mt][nt][r] = 0.f;

    const int NK = K >> 5;

    auto load_tiles = [&](int i) {
        const int st = i % 3;
        const int k0 = i << 5;
        const uint32_t abase = smem_base + (uint32_t)(st * 2 * TILE_WORDS) * 4;
        const uint32_t bbase = abase + TILE_WORDS * 4;
#pragma unroll
        for (int j = 0; j < 4; j++) {
            const int m = ld_row + 32 * j;
            const uint32_t soff = (uint32_t)(m * TSTR + ld_k4) * 4;
            CP_ASYNC16(abase + soff, A + (size_t)(bm + m) * K + k0 + ld_k4);
            CP_ASYNC16(bbase + soff, B + (size_t)(bn + m) * K + k0 + ld_k4);
        }
        CP_ASYNC_COMMIT();
    };

    load_tiles(0);
    load_tiles(1);

    for (int i = 0; i < NK; i++) {
        if (i + 1 < NK) { CP_ASYNC_WAIT(1); }   // newest group (i+1) may stay pending
        else            { CP_ASYNC_WAIT(0); }   // last iter: drain (group i is newest)
        __syncthreads();

        const float* As = smf + (size_t)(i % 3) * 2 * TILE_WORDS;
        const float* Bs = As + TILE_WORDS;

#pragma unroll
        for (int ks = 0; ks < 4; ks++) {
            const int kc = ks * 8 + lc;
            uint32_t af[4][4];
#pragma unroll
            for (int mt = 0; mt < 4; mt++) {
                const int row = wm * 64 + mt * 16 + lr;
                af[mt][0] = __float_as_uint(As[row * TSTR + kc]);
                af[mt][1] = __float_as_uint(As[(row + 8) * TSTR + kc]);
                af[mt][2] = __float_as_uint(As[row * TSTR + kc + 4]);
                af[mt][3] = __float_as_uint(As[(row + 8) * TSTR + kc + 4]);
            }
            uint32_t bf[4][2];
#pragma unroll
            for (int nt = 0; nt < 4; nt++) {
                const int ncol = wn * 32 + nt * 8 + lr;
                bf[nt][0] = __float_as_uint(Bs[ncol * TSTR + kc]);
                bf[nt][1] = __float_as_uint(Bs[ncol * TSTR + kc + 4]);
            }
#pragma unroll
            for (int mt = 0; mt < 4; mt++)
#pragma unroll
                for (int nt = 0; nt < 4; nt++)
                    mma_tf32(c[mt][nt], af[mt], bf[nt]);
        }

        if (i + 2 < NK) load_tiles(i + 2);
    }

#pragma unroll
    for (int nt = 0; nt < 4; nt++) {
        const int col = bn + wn * 32 + nt * 8 + lc * 2;
        float b0 = 0.f, b1 = 0.f;
        if (bias) { b0 = bias[col]; b1 = bias[col + 1]; }
#pragma unroll
        for (int mt = 0; mt < 4; mt++) {
            const int row = bm + wm * 64 + mt * 16 + lr;
            float2 v0 = make_float2(c[mt][nt][0] + b0, c[mt][nt][1] + b1);
            float2 v1 = make_float2(c[mt][nt][2] + b0, c[mt][nt][3] + b1);
            *(float2*)(C + (size_t)row * N + col) = v0;
            *(float2*)(C + (size_t)(row + 8) * N + col) = v1;
        }
    }
}

// ---------------------------------------------------------------------------
// Rotary embedding + tf32 pre-round + q pre-scale
// ---------------------------------------------------------------------------
__global__ void rotary_kernel(float* __restrict__ mixed)
{
    const int s = blockIdx.x;
    const int n = blockIdx.y;
    const int d = threadIdx.x;  // 0..63
    const float inv_freq = expf(-(float)d * (9.210340371976184f / 64.0f));
    const float freq = (float)s * inv_freq;
    float si, c;
    sincosf(freq, &si, &c);
    const float scale = 0.08838834764831845f;

    float* base = mixed + (size_t)s * MIXED_W + n * HEAD_W;
    {
        float* p = base;
        const float x1 = p[d];
        const float x2 = p[d + 64];
        p[d]      = tf32_round(scale * (x1 * c - x2 * si));
        p[d + 64] = tf32_round(scale * (x2 * c + x1 * si));
    }
    {
        float* p = base + HD;
        const float x1 = p[d];
        const float x2 = p[d + 64];
        p[d]      = tf32_round(x1 * c - x2 * si);
        p[d + 64] = tf32_round(x2 * c + x1 * si);
    }
    {
        float* p = base + 2 * HD;
        p[d]      = tf32_round(p[d]);
        p[d + 64] = tf32_round(p[d + 64]);
    }
}

// ---------------------------------------------------------------------------
// tf32 mma.sync flash attention (causal)
// 1-D grid, qt-major descending (big tiles scheduled first).
// ---------------------------------------------------------------------------
#define AQ 128
#define AK 64
#define QST 144
#define QST4 (QST / 4)
#define VST 136
#define QWRD (128 * QST)
#define KWRD (64 * QST)
#define VWRD (64 * VST)
#define ATTN_SMEM_BYTES ((QWRD + 2 * (KWRD + VWRD)) * 4)  // 217088 B
#define NQT (S / AQ)   // 16

__global__ __launch_bounds__(256, 1) void attn_tc_kernel(
    const float* __restrict__ mixed, float* __restrict__ ctx)
{
    extern __shared__ float sf[];
    const uint32_t smem_base = smem_to_u32(sf);

    const int tid  = threadIdx.x;
    const int wid  = tid >> 5;
    const int lane = tid & 31;
    const int lr = lane >> 2;
    const int lc = lane & 3;
    const int bid = blockIdx.x;
    const int h  = bid & (NH - 1);
    const int qt = NQT - 1 - (bid >> 4);   // qt-major, biggest first
    const int r0 = qt * AQ;
    const int m0 = wid * 16;
    const size_t hoff = (size_t)h * HEAD_W;

    auto load_kv = [&](int kt) {
        const int b = kt & 1;
        const uint32_t kb = smem_base + (uint32_t)(QWRD + b * (KWRD + VWRD)) * 4;
        const uint32_t vb = kb + KWRD * 4;
        const float* kg = mixed + (size_t)(kt * AK) * MIXED_W + hoff + HD;
        const float* vg = kg + HD;
#pragma unroll
        for (int it = 0; it < 8; it++) {
            const int u = tid + (it << 8);
            const int row = u >> 5, c4 = (u & 31) << 2;
            CP_ASYNC16(kb + (uint32_t)(row * QST + c4) * 4, kg + (size_t)row * MIXED_W + c4);
            CP_ASYNC16(vb + (uint32_t)(row * VST + c4) * 4, vg + (size_t)row * MIXED_W + c4);
        }
        CP_ASYNC_COMMIT();
    };

    load_kv(0);

    {
        const float* qg = mixed + (size_t)r0 * MIXED_W + hoff;
#pragma unroll
        for (int it = 0; it < 16; it++) {
            const int u = tid + (it << 8);
            const int row = u >> 5, c4 = (u & 31) << 2;
            CP_ASYNC16(smem_base + (uint32_t)(row * QST + c4) * 4,
                       qg + (size_t)row * MIXED_W + c4);
        }
        CP_ASYNC_COMMIT();
    }

    const int nkt = (r0 >> 6) + 2;

    float co[16][4];
#pragma unroll
    for (int nt = 0; nt < 16; nt++)
#pragma unroll
        for (int r = 0; r < 4; r++) co[nt][r] = 0.f;
    float mrow[2] = {-1e30f, -1e30f};
    float lrow[2] = {0.f, 0.f};

    const int src1 = (lane & ~3) | (lc >> 1);
    const int src2 = src1 + 2;
    const bool podd = (lc & 1);

    for (int kt = 0; kt < nkt; kt++) {
        if (kt + 1 < nkt) { load_kv(kt + 1); CP_ASYNC_WAIT(1); }
        else              { CP_ASYNC_WAIT(0); }
        __syncthreads();

        const float* Ks = sf + QWRD + (size_t)(kt & 1) * (KWRD + VWRD);
        const float* Vs = Ks + KWRD;
        const float4* Qs4 = (const float4*)sf;
        const float4* Ks4 = (const float4*)Ks;
        const int c0 = kt * AK;

        if (c0 <= r0 + m0 + 15) {
            float s[8][4];
#pragma unroll
            for (int nt = 0; nt < 8; nt++)
#pragma unroll
                for (int r = 0; r < 4; r++) s[nt][r] = 0.f;

#pragma unroll
            for (int ch = 0; ch < 4; ch++) {
                const int cb = ch * 8;
                const int row = m0 + lr;
                float4 qa[2][2];
                qa[0][0] = Qs4[row * QST4 + cb + lc];
                qa[0][1] = Qs4[row * QST4 + cb + 4 + lc];
                qa[1][0] = Qs4[(row + 8) * QST4 + cb + lc];
                qa[1][1] = Qs4[(row + 8) * QST4 + cb + 4 + lc];
#pragma unroll
                for (int g = 0; g < 2; g++) {
                    float4 kb4[4][2];
#pragma unroll
                    for (int q = 0; q < 4; q++) {
                        const int col = (g * 4 + q) * 8 + lr;
                        kb4[q][0] = Ks4[col * QST4 + cb + lc];
                        kb4[q][1] = Ks4[col * QST4 + cb + 4 + lc];
                    }
#pragma unroll
                    for (int j = 0; j < 4; j++) {
                        uint32_t a[4] = { f4c(qa[0][0], j), f4c(qa[1][0], j),
                                          f4c(qa[0][1], j), f4c(qa[1][1], j) };
#pragma unroll
                        for (int q = 0; q < 4; q++) {
                            uint32_t b[2] = { f4c(kb4[q][0], j), f4c(kb4[q][1], j) };
                            mma_tf32(s[g * 4 + q], a, b);
                        }
                    }
                }
            }

            if (c0 + AK - 1 > r0 + m0) {
                const int rga = r0 + m0 + lr;
                const int rgb = rga + 8;
#pragma unroll
                for (int nt = 0; nt < 8; nt++) {
                    const int cg0 = c0 + nt * 8 + lc * 2;
                    const int cg1 = cg0 + 1;
                    if (cg0 > rga) s[nt][0] = -1e30f;
                    if (cg1 > rga) s[nt][1] = -1e30f;
                    if (cg0 > rgb) s[nt][2] = -1e30f;
                    if (cg1 > rgb) s[nt][3] = -1e30f;
                }
            }

#pragma unroll
            for (int hh = 0; hh < 2; hh++) {
                float mx = -1e30f;
#pragma unroll
                for (int nt = 0; nt < 8; nt++)
                    mx = fmaxf(mx, fmaxf(s[nt][2 * hh], s[nt][2 * hh + 1]));
                mx = fmaxf(mx, __shfl_xor_sync(0xffffffffu, mx, 1));
                mx = fmaxf(mx, __shfl_xor_sync(0xffffffffu, mx, 2));
                const float m_new = fmaxf(mrow[hh], mx);
                const float sc = __expf(mrow[hh] - m_new);
                float rs = 0.f;
#pragma unroll
                for (int nt = 0; nt < 8; nt++) {
                    const float p0 = __expf(s[nt][2 * hh] - m_new);
                    const float p1 = __expf(s[nt][2 * hh + 1] - m_new);
                    s[nt][2 * hh] = p0;
                    s[nt][2 * hh + 1] = p1;
                    rs += p0 + p1;
                }
                rs += __shfl_xor_sync(0xffffffffu, rs, 1);
                rs += __shfl_xor_sync(0xffffffffu, rs, 2);
                lrow[hh] = lrow[hh] * sc + rs;
                mrow[hh] = m_new;
#pragma unroll
                for (int nt = 0; nt < 16; nt++) {
                    co[nt][2 * hh]     *= sc;
                    co[nt][2 * hh + 1] *= sc;
                }
            }

#pragma unroll
            for (int kg = 0; kg < 8; kg++) {
                uint32_t pa[4];
                {
                    const float x0 = __shfl_sync(0xffffffffu, s[kg][0], src1);
                    const float x1 = __shfl_sync(0xffffffffu, s[kg][1], src1);
                    pa[0] = f32_to_tf32(podd ? x1 : x0);
                    const float x2 = __shfl_sync(0xffffffffu, s[kg][2], src1);
                    const float x3 = __shfl_sync(0xffffffffu, s[kg][3], src1);
                    pa[1] = f32_to_tf32(podd ? x3 : x2);
                    const float y0 = __shfl_sync(0xffffffffu, s[kg][0], src2);
                    const float y1 = __shfl_sync(0xffffffffu, s[kg][1], src2);
                    pa[2] = f32_to_tf32(podd ? y1 : y0);
                    const float y2 = __shfl_sync(0xffffffffu, s[kg][2], src2);
                    const float y3 = __shfl_sync(0xffffffffu, s[kg][3], src2);
                    pa[3] = f32_to_tf32(podd ? y3 : y2);
                }
#pragma unroll
                for (int nt = 0; nt < 16; nt++) {
                    uint32_t vb[2];
                    vb[0] = __float_as_uint(Vs[(kg * 8 + lc) * VST + nt * 8 + lr]);
                    vb[1] = __float_as_uint(Vs[(kg * 8 + lc + 4) * VST + nt * 8 + lr]);
                    mma_tf32(co[nt], pa, vb);
                }
            }
        }
        __syncthreads();
    }

    {
        const float li0 = 1.f / lrow[0];
        const float li1 = 1.f / lrow[1];
        const int row = r0 + m0 + lr;
#pragma unroll
        for (int nt = 0; nt < 16; nt++) {
            const int col = h * HD + nt * 8 + lc * 2;
            *(float2*)(ctx + (size_t)row * H + col) =
                make_float2(tf32_round(co[nt][0] * li0), tf32_round(co[nt][1] * li0));
            *(float2*)(ctx + (size_t)(row + 8) * H + col) =
                make_float2(tf32_round(co[nt][2] * li1), tf32_round(co[nt][3] * li1));
        }
    }
}

// ---------------------------------------------------------------------------
// Launch
// ---------------------------------------------------------------------------
extern "C" void kernel_launch(void* const* d_in, const int* in_sizes, int n_in,
                              void* d_out, int out_size)
{
    const float* hidden  = (const float*)d_in[0];
    const float* w_qkv   = (const float*)d_in[2];
    const float* b_qkv   = (const float*)d_in[3];
    const float* w_dense = (const float*)d_in[4];
    float* out = (float*)d_out;

    float *mixed, *ctx, *hidden_t, *wqkv_t, *wdense_t;
    cudaGetSymbolAddress((void**)&mixed, g_mixed);
    cudaGetSymbolAddress((void**)&ctx, g_ctx);
    cudaGetSymbolAddress((void**)&hidden_t, g_hidden_t);
    cudaGetSymbolAddress((void**)&wqkv_t, g_wqkv_t);
    cudaGetSymbolAddress((void**)&wdense_t, g_wdense_t);

    cudaFuncSetAttribute(gemm_tc_kernel,
                         cudaFuncAttributeMaxDynamicSharedMemorySize, GT_SMEM_BYTES);
    cudaFuncSetAttribute(attn_tc_kernel,
                         cudaFuncAttributeMaxDynamicSharedMemorySize, ATTN_SMEM_BYTES);

    // 0) fused tf32 pre-round of all GEMM operands (one launch)
    round_all_kernel<<<2048, 256>>>((const float4*)hidden, (const float4*)w_qkv,
                                    (const float4*)w_dense, (float4*)hidden_t,
                                    (float4*)wqkv_t, (float4*)wdense_t);

    // 1) QKV projection
    {
        dim3 grid(QKV_N / 128, S / 128);
        gemm_tc_kernel<<<grid, 256, GT_SMEM_BYTES>>>(hidden_t, wqkv_t, b_qkv,
                                                     mixed, S, QKV_N, H);
    }

    // 2) Rotary + tf32 pre-round of q/k/v
    {
        dim3 grid(S, NH);
        rotary_kernel<<<grid, 64>>>(mixed);
    }

    // 3) Causal flash attention (1-D grid, qt-major descending)
    attn_tc_kernel<<<NQT * NH, 256, ATTN_SMEM_BYTES>>>(mixed, ctx);

    // 4) Dense projection
    {
        dim3 grid(H / 128, S / 128);
        gemm_tc_kernel<<<grid, 256, GT_SMEM_BYTES>>>(ctx, wdense_t, nullptr,
                                                     out, S, H, H);
    }
}